// round 8
// baseline (speedup 1.0000x reference)
#include <cuda_runtime.h>
#include <cuda_bf16.h>
#include <cstdint>

#define B_SZ 1024
#define F_SZ 256
#define D_SZ 64
#define GRID_MAIN 148
#define NUNITS 2048   // 2 halves x 1024 batches

// ---------------- device scratch ----------------
__device__ float g_qkv[3 * F_SZ * D_SZ];     // qkv[t][f][d]
__device__ float g_trans[2 * F_SZ * D_SZ];   // trans[t][f][d]
__device__ float g_q2T[D_SZ * F_SZ];         // q2T[d][j] = qkv2[j][d]
__device__ float g_q2rowmax[F_SZ];           // max_d |qkv2[j][d]|
__device__ float g_S1[B_SZ * F_SZ];          // s1[b][j]
__device__ float g_SA[B_SZ * F_SZ];          // s0*s2 [b][i]
__device__ float g_Zs[B_SZ];                 // exact max_j,d |Z[b][j,d]|
__device__ float g_sMr[F_SZ];                // per-row M scale = rowmax/127
__device__ char  g_M1[F_SZ * F_SZ];          // M hi int8 (row-scaled)
__device__ char  g_M0[F_SZ * F_SZ];          // M lo int8

// ---------------- smem layout for k_main (bytes) ----------------
#define AP_STR 272                            // padded row (256 + 16), 17*16
#define SM_Q2T 0                              // 65536 (fp32 q2T)
#define SM_A1  65536                          // 128*272 = 34816
#define SM_A0  (SM_A1 + 34816)                // 100352
#define SM_ZT  (SM_A0 + 34816)                // 135168; [buf][plane] 64*272 each
#define ZT_PLANE 17408
#define ZT_BUF   (2 * ZT_PLANE)
#define SM_S1B (SM_ZT + 2 * ZT_BUF)           // 204800 (256 fp32)
#define SMEM_TOTAL (SM_S1B + 1024)            // 205824

// ---------------- helpers ----------------
__device__ __forceinline__ uint32_t smem_u32(const void* p) {
    uint32_t a;
    asm("{ .reg .u64 t; cvta.to.shared.u64 t, %1; cvt.u32.u64 %0, t; }"
        : "=r"(a) : "l"(p));
    return a;
}
#define LDSM4(r, a) \
    asm volatile("ldmatrix.sync.aligned.m8n8.x4.shared.b16 {%0,%1,%2,%3}, [%4];" \
                 : "=r"((r)[0]), "=r"((r)[1]), "=r"((r)[2]), "=r"((r)[3]) : "r"(a))
#define IMMA(d, a, b0, b1) \
    asm volatile("mma.sync.aligned.m16n8k32.row.col.s32.s8.s8.s32 " \
                 "{%0,%1,%2,%3}, {%4,%5,%6,%7}, {%8,%9}, {%0,%1,%2,%3};" \
                 : "+r"((d)[0]), "+r"((d)[1]), "+r"((d)[2]), "+r"((d)[3]) \
                 : "r"((a)[0]), "r"((a)[1]), "r"((a)[2]), "r"((a)[3]), \
                   "r"(b0), "r"(b1))

// ---------------- K1: qkv / trans = indicator @ W (+ q2T, q2rowmax) ----------------
__global__ void k_qkv(const float* __restrict__ ind,
                      const float* __restrict__ Wqk,
                      const float* __restrict__ Wqkv) {
    int m = blockIdx.y;
    int fl = threadIdx.x >> 6, e = threadIdx.x & 63;
    int f = blockIdx.x * 4 + fl;
    __shared__ float indS[4 * D_SZ];
    __shared__ float pm[8];
    indS[threadIdx.x] = ind[f * D_SZ + e];
    __syncthreads();
    const float* W = (m < 3) ? (Wqkv + m * D_SZ * D_SZ)
                             : (Wqk + (m - 3) * D_SZ * D_SZ);
    float acc = 0.f;
#pragma unroll
    for (int d = 0; d < D_SZ; d++) acc = fmaf(indS[fl * 64 + d], W[d * D_SZ + e], acc);
    if (m < 3) {
        g_qkv[m * F_SZ * D_SZ + f * D_SZ + e] = acc;
        if (m == 2) {
            g_q2T[e * F_SZ + f] = acc;
            float av = fabsf(acc);
#pragma unroll
            for (int o = 16; o > 0; o >>= 1)
                av = fmaxf(av, __shfl_xor_sync(0xFFFFFFFFu, av, o));
            if ((threadIdx.x & 31) == 0) pm[threadIdx.x >> 5] = av;
        }
    } else {
        g_trans[(m - 3) * F_SZ * D_SZ + f * D_SZ + e] = acc;
    }
    __syncthreads();
    if (m == 2 && threadIdx.x < 4)
        g_q2rowmax[blockIdx.x * 4 + threadIdx.x] =
            fmaxf(pm[2 * threadIdx.x], pm[2 * threadIdx.x + 1]);
}

// ---------------- K2: merged gate-quant + s + Zs ----------------
__global__ void __launch_bounds__(256) k_prep(const float* __restrict__ feature) {
    int tid = threadIdx.x, w = tid >> 5, l = tid & 31;
    __shared__ float rowv[256];
    __shared__ float redm[8];
    __shared__ float zbuf[8][2][2];
    if (blockIdx.x < 256) {
        // ---- gate row i: M[i][j] = cross*(logits>0); int8 row-scaled split ----
        int i = blockIdx.x;
        __shared__ float q1i[D_SZ], t0i[D_SZ];
        if (tid < 64) q1i[tid] = g_qkv[F_SZ * D_SZ + i * D_SZ + tid];
        else if (tid < 128) t0i[tid - 64] = g_trans[i * D_SZ + (tid - 64)];
        __syncthreads();
        const float* q0 = g_qkv;
        const float* t1 = g_trans + F_SZ * D_SZ;
        for (int jj = 0; jj < 32; jj++) {
            int j = w * 32 + jj;
            float c  = q1i[l] * q0[j * D_SZ + l] + q1i[l + 32] * q0[j * D_SZ + l + 32];
            float gl = t0i[l] * t1[j * D_SZ + l] + t0i[l + 32] * t1[j * D_SZ + l + 32];
#pragma unroll
            for (int o = 16; o > 0; o >>= 1) {
                c  += __shfl_xor_sync(0xFFFFFFFFu, c, o);
                gl += __shfl_xor_sync(0xFFFFFFFFu, gl, o);
            }
            if (l == 0) rowv[j] = (gl > 0.f) ? c : 0.f;
        }
        __syncthreads();
        float v = fabsf(rowv[tid]);
#pragma unroll
        for (int o = 16; o > 0; o >>= 1)
            v = fmaxf(v, __shfl_xor_sync(0xFFFFFFFFu, v, o));
        if (l == 0) redm[w] = v;
        __syncthreads();
        if (tid == 0) {
            float mx = redm[0];
#pragma unroll
            for (int k = 1; k < 8; k++) mx = fmaxf(mx, redm[k]);
            redm[0] = mx;
            g_sMr[i] = mx * (1.f / 127.f);
        }
        __syncthreads();
        float rmax = redm[0];
        float inv = rmax > 0.f ? 127.f / rmax : 0.f;
        float q = rowv[tid] * inv;
        int q1 = __float2int_rn(q);
        int q0i = __float2int_rn((q - (float)q1) * 128.f);
        g_M1[i * F_SZ + tid] = (char)q1;
        g_M0[i * F_SZ + tid] = (char)q0i;
    } else {
        // ---- s: S1, SA, and exact per-batch Zmax ----
        int b0 = (blockIdx.x - 256) * 4;
        int hb = l >> 4, ll = l & 15;
        float zm[2] = {0.f, 0.f};
        for (int ii = 0; ii < 32; ii++) {
            int i = w * 32 + ii;
            const float4* qp = (const float4*)(g_qkv + i * D_SZ) + ll;
            float4 q0 = qp[0];
            float4 q1 = qp[(F_SZ * D_SZ) / 4];
            float4 q2 = qp[(2 * F_SZ * D_SZ) / 4];
            float q2rm = __ldg(g_q2rowmax + i);
#pragma unroll
            for (int bp = 0; bp < 2; bp++) {
                int b = b0 + bp * 2 + hb;
                float4 f = *((const float4*)(feature + (size_t)b * (F_SZ * D_SZ)
                                             + i * D_SZ) + ll);
                float d0 = f.x * q0.x + f.y * q0.y + f.z * q0.z + f.w * q0.w;
                float d1 = f.x * q1.x + f.y * q1.y + f.z * q1.z + f.w * q1.w;
                float d2 = f.x * q2.x + f.y * q2.y + f.z * q2.z + f.w * q2.w;
#pragma unroll
                for (int o = 8; o > 0; o >>= 1) {
                    d0 += __shfl_xor_sync(0xFFFFFFFFu, d0, o);
                    d1 += __shfl_xor_sync(0xFFFFFFFFu, d1, o);
                    d2 += __shfl_xor_sync(0xFFFFFFFFu, d2, o);
                }
                zm[bp] = fmaxf(zm[bp], fabsf(d1) * q2rm);
                if (ll == 0) {
                    g_S1[b * F_SZ + i] = d1;
                    g_SA[b * F_SZ + i] = d0 * d2;
                }
            }
        }
        if (ll == 0) { zbuf[w][hb][0] = zm[0]; zbuf[w][hb][1] = zm[1]; }
        __syncthreads();
        if (tid < 4) {
            int bp = tid >> 1, h2 = tid & 1;
            float mx = 0.f;
#pragma unroll
            for (int w2 = 0; w2 < 8; w2++) mx = fmaxf(mx, zbuf[w2][h2][bp]);
            g_Zs[b0 + bp * 2 + h2] = mx;
        }
    }
}

// ---------------- producer: build quantized ZT (int8 hi/lo) ----------------
__device__ __forceinline__ void build_zt(char* sm, int b, int buf, int ptid) {
    float4* s1d = (float4*)(sm + SM_S1B);
    if (ptid < 64) s1d[ptid] = ((const float4*)(g_S1 + b * F_SZ))[ptid];
    asm volatile("bar.sync 1, 256;" ::: "memory");
    float zs = __ldg(g_Zs + b);
    float inv = zs > 0.f ? 127.f / zs : 0.f;
    const float4* q2s = (const float4*)(sm + SM_Q2T);
    char* zt1 = sm + SM_ZT + buf * ZT_BUF;
    char* zt0 = zt1 + ZT_PLANE;
    for (int idx = ptid; idx < 4096; idx += 256) {
        int d = idx >> 6, jc = idx & 63;
        float4 q = q2s[d * 64 + jc];
        float4 s = s1d[jc];
        uint32_t p1 = 0, p0 = 0;
        float z, zq; int z1, z0;
        z = q.x * s.x; zq = z * inv; z1 = __float2int_rn(zq);
        z0 = __float2int_rn((zq - (float)z1) * 128.f);
        p1 |= (uint32_t)(z1 & 255); p0 |= (uint32_t)(z0 & 255);
        z = q.y * s.y; zq = z * inv; z1 = __float2int_rn(zq);
        z0 = __float2int_rn((zq - (float)z1) * 128.f);
        p1 |= (uint32_t)(z1 & 255) << 8; p0 |= (uint32_t)(z0 & 255) << 8;
        z = q.z * s.z; zq = z * inv; z1 = __float2int_rn(zq);
        z0 = __float2int_rn((zq - (float)z1) * 128.f);
        p1 |= (uint32_t)(z1 & 255) << 16; p0 |= (uint32_t)(z0 & 255) << 16;
        z = q.w * s.w; zq = z * inv; z1 = __float2int_rn(zq);
        z0 = __float2int_rn((zq - (float)z1) * 128.f);
        p1 |= (uint32_t)(z1 & 255) << 24; p0 |= (uint32_t)(z0 & 255) << 24;
        *(uint32_t*)(zt1 + d * AP_STR + jc * 4) = p1;
        *(uint32_t*)(zt0 + d * AP_STR + jc * 4) = p0;
    }
}

// ---------------- K3: persistent IMMA main kernel (warp-specialized) ----------------
__global__ void __launch_bounds__(512, 1)
k_main(float* __restrict__ out) {
    extern __shared__ char sm[];
    uint32_t sb = smem_u32(sm);
    int tid = threadIdx.x, w = tid >> 5, lane = tid & 31;
    int cidx = blockIdx.x;
    int u0 = (cidx * NUNITS) / GRID_MAIN, u1 = ((cidx + 1) * NUNITS) / GRID_MAIN;
    bool isCompute = (w < 8);

    // load q2T (fp32) into smem once
    {
        const float4* src = (const float4*)g_q2T;
        float4* dst = (float4*)(sm + SM_Q2T);
        for (int i = tid; i < 4096; i += 512) dst[i] = src[i];
    }
    __syncthreads();
    if (!isCompute) build_zt(sm, u0 & 1023, 0, tid - 256);
    __syncthreads();

    // compute-warp geometry
    int m0r = (w >> 1) * 32, n0r = (w & 1) * 32;
    int g = lane >> 2, t4 = lane & 3;
    int at = lane >> 3;
    uint32_t aRow = (uint32_t)((at & 1) * 8 + (lane & 7));
    uint32_t aBo = (uint32_t)((at >> 1) * 16);
    uint32_t aAddr1 = sb + SM_A1 + (uint32_t)(m0r + aRow) * AP_STR + aBo;
    uint32_t aAddr0 = aAddr1 + (SM_A0 - SM_A1);
    uint32_t bRow = (uint32_t)((at >> 1) * 8 + (lane & 7));
    uint32_t bBo = (uint32_t)((at & 1) * 16);

    int curH = -1;
    for (int u = u0; u < u1; u++) {
        int h = u >> 10, b = u & 1023;
        int cur = (u - u0) & 1, nxt = cur ^ 1;
        if (h != curH) {
            const uint32_t* m1 = (const uint32_t*)(g_M1 + h * 128 * F_SZ);
            const uint32_t* m0p = (const uint32_t*)(g_M0 + h * 128 * F_SZ);
            for (int idx = tid; idx < 8192; idx += 512) {
                int r = idx >> 6, c4 = idx & 63;
                *(uint32_t*)(sm + SM_A1 + r * AP_STR + c4 * 4) = m1[idx];
                *(uint32_t*)(sm + SM_A0 + r * AP_STR + c4 * 4) = m0p[idx];
            }
            curH = h;
            __syncthreads();
        }
        if (isCompute) {
            uint32_t zb = sb + SM_ZT + (uint32_t)cur * ZT_BUF;
            uint32_t bAddr1 = zb + (uint32_t)(n0r + bRow) * AP_STR + bBo;
            uint32_t bAddr0 = bAddr1 + ZT_PLANE;
            int32_t acc1[8][4], acc2[8][4];
#pragma unroll
            for (int i = 0; i < 8; i++)
#pragma unroll
                for (int q = 0; q < 4; q++) { acc1[i][q] = 0; acc2[i][q] = 0; }

#pragma unroll
            for (int k = 0; k < 8; k++) {
                uint32_t ko = (uint32_t)k * 32;
                uint32_t a1f0[4], a1f1[4], a0f0[4], a0f1[4];
                LDSM4(a1f0, aAddr1 + ko);
                LDSM4(a1f1, aAddr1 + 16 * AP_STR + ko);
                LDSM4(a0f0, aAddr0 + ko);
                LDSM4(a0f1, aAddr0 + 16 * AP_STR + ko);
                uint32_t b1f0[4], b1f1[4], b0f0[4], b0f1[4];
                LDSM4(b1f0, bAddr1 + ko);
                LDSM4(b1f1, bAddr1 + 16 * AP_STR + ko);
                LDSM4(b0f0, bAddr0 + ko);
                LDSM4(b0f1, bAddr0 + 16 * AP_STR + ko);

                IMMA(acc1[0], a1f0, b1f0[0], b1f0[1]);
                IMMA(acc1[1], a1f0, b1f0[2], b1f0[3]);
                IMMA(acc1[2], a1f0, b1f1[0], b1f1[1]);
                IMMA(acc1[3], a1f0, b1f1[2], b1f1[3]);
                IMMA(acc1[4], a1f1, b1f0[0], b1f0[1]);
                IMMA(acc1[5], a1f1, b1f0[2], b1f0[3]);
                IMMA(acc1[6], a1f1, b1f1[0], b1f1[1]);
                IMMA(acc1[7], a1f1, b1f1[2], b1f1[3]);

                IMMA(acc2[0], a1f0, b0f0[0], b0f0[1]);
                IMMA(acc2[1], a1f0, b0f0[2], b0f0[3]);
                IMMA(acc2[2], a1f0, b0f1[0], b0f1[1]);
                IMMA(acc2[3], a1f0, b0f1[2], b0f1[3]);
                IMMA(acc2[4], a1f1, b0f0[0], b0f0[1]);
                IMMA(acc2[5], a1f1, b0f0[2], b0f0[3]);
                IMMA(acc2[6], a1f1, b0f1[0], b0f1[1]);
                IMMA(acc2[7], a1f1, b0f1[2], b0f1[3]);

                IMMA(acc2[0], a0f0, b1f0[0], b1f0[1]);
                IMMA(acc2[1], a0f0, b1f0[2], b1f0[3]);
                IMMA(acc2[2], a0f0, b1f1[0], b1f1[1]);
                IMMA(acc2[3], a0f0, b1f1[2], b1f1[3]);
                IMMA(acc2[4], a0f1, b1f0[0], b1f0[1]);
                IMMA(acc2[5], a0f1, b1f0[2], b1f0[3]);
                IMMA(acc2[6], a0f1, b1f1[0], b1f1[1]);
                IMMA(acc2[7], a0f1, b1f1[2], b1f1[3]);
            }

            // epilogue: dequant + SA scale + store
            float sZ = __ldg(g_Zs + b) * (1.f / 127.f);
            const float* sap = g_SA + b * F_SZ + h * 128;
            const float* smr = g_sMr + h * 128;
            float* ob = out + (size_t)b * (F_SZ * D_SZ) + h * 128 * D_SZ;
#pragma unroll
            for (int mt = 0; mt < 2; mt++) {
                int r0 = m0r + mt * 16 + g;
                float f0 = __ldg(sap + r0) * __ldg(smr + r0) * sZ;
                float f1 = __ldg(sap + r0 + 8) * __ldg(smr + r0 + 8) * sZ;
#pragma unroll
                for (int nt = 0; nt < 4; nt++) {
                    const int32_t* A1 = acc1[mt * 4 + nt];
                    const int32_t* A2 = acc2[mt * 4 + nt];
                    int col = n0r + nt * 8 + 2 * t4;
                    float2 v0, v1;
                    v0.x = ((float)A1[0] + (float)A2[0] * 0.0078125f) * f0;
                    v0.y = ((float)A1[1] + (float)A2[1] * 0.0078125f) * f0;
                    v1.x = ((float)A1[2] + (float)A2[2] * 0.0078125f) * f1;
                    v1.y = ((float)A1[3] + (float)A2[3] * 0.0078125f) * f1;
                    *(float2*)(ob + r0 * 64 + col) = v0;
                    *(float2*)(ob + (r0 + 8) * 64 + col) = v1;
                }
            }
        } else {
            if (u + 1 < u1) build_zt(sm, (u + 1) & 1023, nxt, tid - 256);
        }
        __syncthreads();
    }
}

// ---------------- launch ----------------
extern "C" void kernel_launch(void* const* d_in, const int* in_sizes, int n_in,
                              void* d_out, int out_size) {
    const float *feature = nullptr, *indicator = nullptr;
    const float *Wqk = nullptr, *Wqkv = nullptr;
    for (int k = 0; k < n_in; k++) {
        switch (in_sizes[k]) {
            case B_SZ * F_SZ * D_SZ: feature   = (const float*)d_in[k]; break;
            case F_SZ * D_SZ:        indicator = (const float*)d_in[k]; break;
            case 2 * D_SZ * D_SZ:    Wqk       = (const float*)d_in[k]; break;
            case 3 * D_SZ * D_SZ:    Wqkv      = (const float*)d_in[k]; break;
        }
    }
    float* out = (float*)d_out;

    cudaFuncSetAttribute(k_main, cudaFuncAttributeMaxDynamicSharedMemorySize,
                         SMEM_TOTAL);

    k_qkv<<<dim3(64, 5), 256>>>(indicator, Wqk, Wqkv);
    k_prep<<<512, 256>>>(feature);
    k_main<<<GRID_MAIN, 512, SMEM_TOTAL>>>(out);
}

// round 10
// speedup vs baseline: 3.0842x; 3.0842x over previous
#include <cuda_runtime.h>
#include <cuda_fp16.h>
#include <cstdint>

#define B_SZ 1024
#define F_SZ 256
#define D_SZ 64
#define GRID_MAIN 148

// ---------------- device scratch ----------------
__device__ float  g_qkv[3 * F_SZ * D_SZ];    // qkv[t][f][d]
__device__ float  g_trans[2 * F_SZ * D_SZ];  // trans[t][f][d]
__device__ float  g_S1[B_SZ * F_SZ];         // s1[b][j]
__device__ float  g_SA[B_SZ * F_SZ];         // s0*s2 [b][i]
__device__ __half g_Mh[F_SZ * F_SZ];         // gated cross, fp16

// ---------------- smem layout for k_main (bytes) ----------------
#define A_STRH 264                            // halfs per A row (256+8)
#define A_RB   (A_STRH * 2)                   // 528 bytes
#define Z_STRH 72                             // halfs per Z row (64+8)
#define Z_RB   (Z_STRH * 2)                   // 144 bytes
#define SM_A 0                                // 256*528 = 135168
#define SM_Z 135168                           // 256*144 = 36864
#define SMEM_TOTAL (SM_Z + F_SZ * Z_RB)       // 172032

// ---------------- helpers ----------------
__device__ __forceinline__ uint32_t smem_u32(const void* p) {
    uint32_t a;
    asm("{ .reg .u64 t; cvta.to.shared.u64 t, %1; cvt.u32.u64 %0, t; }"
        : "=r"(a) : "l"(p));
    return a;
}
#define LDSM4(r, a) \
    asm volatile("ldmatrix.sync.aligned.m8n8.x4.shared.b16 {%0,%1,%2,%3}, [%4];" \
                 : "=r"((r)[0]), "=r"((r)[1]), "=r"((r)[2]), "=r"((r)[3]) : "r"(a))
#define LDSM4T(r, a) \
    asm volatile("ldmatrix.sync.aligned.m8n8.x4.trans.shared.b16 {%0,%1,%2,%3}, [%4];" \
                 : "=r"((r)[0]), "=r"((r)[1]), "=r"((r)[2]), "=r"((r)[3]) : "r"(a))
#define HMMA(d, a, b0, b1) \
    asm volatile("mma.sync.aligned.m16n8k16.row.col.f32.f16.f16.f32 " \
                 "{%0,%1,%2,%3}, {%4,%5,%6,%7}, {%8,%9}, {%0,%1,%2,%3};" \
                 : "+f"((d)[0]), "+f"((d)[1]), "+f"((d)[2]), "+f"((d)[3]) \
                 : "r"((a)[0]), "r"((a)[1]), "r"((a)[2]), "r"((a)[3]), \
                   "r"(b0), "r"(b1))

__device__ __forceinline__ uint32_t pack2h(float a, float b) {
    __half2 h = __floats2half2_rn(a, b);
    return *(uint32_t*)&h;
}

// ---------------- K1: qkv / trans = indicator @ W ----------------
__global__ void k_qkv(const float* __restrict__ ind,
                      const float* __restrict__ Wqk,
                      const float* __restrict__ Wqkv) {
    int m = blockIdx.y;
    int fl = threadIdx.x >> 6, e = threadIdx.x & 63;
    int f = blockIdx.x * 4 + fl;
    __shared__ float indS[4 * D_SZ];
    indS[threadIdx.x] = ind[f * D_SZ + e];
    __syncthreads();
    const float* W = (m < 3) ? (Wqkv + m * D_SZ * D_SZ)
                             : (Wqk + (m - 3) * D_SZ * D_SZ);
    float acc = 0.f;
#pragma unroll
    for (int d = 0; d < D_SZ; d++) acc = fmaf(indS[fl * 64 + d], W[d * D_SZ + e], acc);
    if (m < 3) g_qkv[m * F_SZ * D_SZ + f * D_SZ + e] = acc;
    else       g_trans[(m - 3) * F_SZ * D_SZ + f * D_SZ + e] = acc;
}

// ---------------- K2: merged gate + s kernel ----------------
// blocks [0,256): gate rows (fp16 M); blocks [256,768): S1/SA, 2 batches each.
__global__ void __launch_bounds__(256) k_prep(const float* __restrict__ feature) {
    int tid = threadIdx.x, w = tid >> 5, l = tid & 31;
    if (blockIdx.x < 256) {
        int i = blockIdx.x;
        __shared__ float q1i[D_SZ], t0i[D_SZ];
        if (tid < 64) q1i[tid] = g_qkv[F_SZ * D_SZ + i * D_SZ + tid];
        else if (tid < 128) t0i[tid - 64] = g_trans[i * D_SZ + (tid - 64)];
        __syncthreads();
        const float* q0 = g_qkv;
        const float* t1 = g_trans + F_SZ * D_SZ;
        for (int jj = 0; jj < 32; jj++) {
            int j = w * 32 + jj;
            float c  = q1i[l] * q0[j * D_SZ + l] + q1i[l + 32] * q0[j * D_SZ + l + 32];
            float gl = t0i[l] * t1[j * D_SZ + l] + t0i[l + 32] * t1[j * D_SZ + l + 32];
#pragma unroll
            for (int o = 16; o > 0; o >>= 1) {
                c  += __shfl_xor_sync(0xFFFFFFFFu, c, o);
                gl += __shfl_xor_sync(0xFFFFFFFFu, gl, o);
            }
            if (l == 0)
                g_Mh[i * F_SZ + j] = __float2half_rn((gl > 0.f) ? c : 0.f);
        }
    } else {
        // S1/SA for 2 batches; half-warps split batches, 16-lane dot products.
        int b0 = (blockIdx.x - 256) * 2;
        int hb = l >> 4, ll = l & 15;
        int b = b0 + hb;
        for (int ii = 0; ii < 32; ii++) {
            int i = w * 32 + ii;
            const float4* qp = (const float4*)(g_qkv + i * D_SZ) + ll;
            float4 q0 = qp[0];
            float4 q1 = qp[(F_SZ * D_SZ) / 4];
            float4 q2 = qp[(2 * F_SZ * D_SZ) / 4];
            float4 f = *((const float4*)(feature + (size_t)b * (F_SZ * D_SZ)
                                         + i * D_SZ) + ll);
            float d0 = f.x * q0.x + f.y * q0.y + f.z * q0.z + f.w * q0.w;
            float d1 = f.x * q1.x + f.y * q1.y + f.z * q1.z + f.w * q1.w;
            float d2 = f.x * q2.x + f.y * q2.y + f.z * q2.z + f.w * q2.w;
#pragma unroll
            for (int o = 8; o > 0; o >>= 1) {
                d0 += __shfl_xor_sync(0xFFFFFFFFu, d0, o);
                d1 += __shfl_xor_sync(0xFFFFFFFFu, d1, o);
                d2 += __shfl_xor_sync(0xFFFFFFFFu, d2, o);
            }
            if (ll == 0) {
                g_S1[b * F_SZ + i] = d1;
                g_SA[b * F_SZ + i] = d0 * d2;
            }
        }
    }
}

// ---------------- K3: persistent fp16 HMMA main kernel ----------------
// One unit = one batch. Full M (256x256 fp16) resident in smem; per batch
// build Z[j][d] = S1[b,j]*Q2[j,d] (fp16) then one 256x64x256 GEMM by 16 warps
// (warp tile 32x32, full K), epilogue scales by SA and stores.
__global__ void __launch_bounds__(512, 1)
k_main(float* __restrict__ out) {
    extern __shared__ char sm[];
    uint32_t sb = smem_u32(sm);
    int tid = threadIdx.x, w = tid >> 5, lane = tid & 31;
    int c = blockIdx.x;
    int b0 = (c * B_SZ) / GRID_MAIN, b1 = ((c + 1) * B_SZ) / GRID_MAIN;

    // load full M (fp16) into padded smem
    {
        const uint4* msrc = (const uint4*)g_Mh;   // 8 halfs per uint4
        for (int i = tid; i < 8192; i += 512) {
            int r = i >> 5, c8 = i & 31;
            *(uint4*)(sm + SM_A + r * A_RB + c8 * 16) = msrc[i];
        }
    }

    // warp geometry: 16 warps, tile (32 m) x (32 n), full K=256
    int m0 = (w >> 1) * 32, n0 = (w & 1) * 32;
    int g = lane >> 2, t4 = lane & 3;
    uint32_t aBase = sb + SM_A + (uint32_t)(m0 + (lane & 15)) * A_RB
                     + (uint32_t)(lane >> 4) * 16;
    uint32_t bBase = sb + SM_Z + (uint32_t)(lane & 15) * Z_RB
                     + (uint32_t)(n0 + 8 * (lane >> 4)) * 2;

    const float* q2 = g_qkv + 2 * F_SZ * D_SZ;

    for (int b = b0; b < b1; b++) {
        __syncthreads();   // protect Z (and first-iter A) vs readers
        // ---- build Z (fp16): thread handles 8 d's of row j ----
        const float* s1p = g_S1 + b * F_SZ;
        for (int idx = tid; idx < 2048; idx += 512) {
            int j = idx >> 3, dq = idx & 7;
            float s1 = __ldg(s1p + j);
            const float4* qp = (const float4*)(q2 + j * 64) + dq * 2;
            float4 qa = qp[0], qb = qp[1];
            uint4 v;
            v.x = pack2h(qa.x * s1, qa.y * s1);
            v.y = pack2h(qa.z * s1, qa.w * s1);
            v.z = pack2h(qb.x * s1, qb.y * s1);
            v.w = pack2h(qb.z * s1, qb.w * s1);
            *(uint4*)(sm + SM_Z + j * Z_RB + dq * 16) = v;
        }
        __syncthreads();

        // ---- mainloop ----
        float acc[8][4];
#pragma unroll
        for (int i = 0; i < 8; i++)
#pragma unroll
            for (int q = 0; q < 4; q++) acc[i][q] = 0.f;

#pragma unroll
        for (int k = 0; k < 16; k++) {
            uint32_t kA = (uint32_t)k * 32;          // 16 halfs along row
            uint32_t kB = (uint32_t)k * 16 * Z_RB;   // 16 Z rows
            uint32_t a0[4], a1[4], bq0[4], bq1[4];
            LDSM4(a0, aBase + kA);
            LDSM4(a1, aBase + 16 * A_RB + kA);
            LDSM4T(bq0, bBase + kB);
            LDSM4T(bq1, bBase + kB + 32);

            HMMA(acc[0], a0, bq0[0], bq0[1]);
            HMMA(acc[1], a0, bq0[2], bq0[3]);
            HMMA(acc[2], a0, bq1[0], bq1[1]);
            HMMA(acc[3], a0, bq1[2], bq1[3]);
            HMMA(acc[4], a1, bq0[0], bq0[1]);
            HMMA(acc[5], a1, bq0[2], bq0[3]);
            HMMA(acc[6], a1, bq1[0], bq1[1]);
            HMMA(acc[7], a1, bq1[2], bq1[3]);
        }

        // ---- epilogue: scale by SA, direct store ----
        const float* sap = g_SA + b * F_SZ;
        float* ob = out + (size_t)b * (F_SZ * D_SZ);
#pragma unroll
        for (int mt = 0; mt < 2; mt++) {
            int r0 = m0 + mt * 16 + g;
            float f0 = __ldg(sap + r0), f1 = __ldg(sap + r0 + 8);
#pragma unroll
            for (int nt = 0; nt < 4; nt++) {
                float* a = acc[mt * 4 + nt];
                int col = n0 + nt * 8 + 2 * t4;
                *(float2*)(ob + r0 * 64 + col) =
                    make_float2(a[0] * f0, a[1] * f0);
                *(float2*)(ob + (r0 + 8) * 64 + col) =
                    make_float2(a[2] * f1, a[3] * f1);
            }
        }
    }
}

// ---------------- launch ----------------
extern "C" void kernel_launch(void* const* d_in, const int* in_sizes, int n_in,
                              void* d_out, int out_size) {
    const float *feature = nullptr, *indicator = nullptr;
    const float *Wqk = nullptr, *Wqkv = nullptr;
    for (int k = 0; k < n_in; k++) {
        switch (in_sizes[k]) {
            case B_SZ * F_SZ * D_SZ: feature   = (const float*)d_in[k]; break;
            case F_SZ * D_SZ:        indicator = (const float*)d_in[k]; break;
            case 2 * D_SZ * D_SZ:    Wqk       = (const float*)d_in[k]; break;
            case 3 * D_SZ * D_SZ:    Wqkv      = (const float*)d_in[k]; break;
        }
    }
    float* out = (float*)d_out;

    cudaFuncSetAttribute(k_main, cudaFuncAttributeMaxDynamicSharedMemorySize,
                         SMEM_TOTAL);

    k_qkv<<<dim3(64, 5), 256>>>(indicator, Wqk, Wqkv);
    k_prep<<<768, 256>>>(feature);
    k_main<<<GRID_MAIN, 512, SMEM_TOTAL>>>(out);
}

// round 11
// speedup vs baseline: 3.1662x; 1.0266x over previous
#include <cuda_runtime.h>
#include <cuda_fp16.h>
#include <cstdint>

#define B_SZ 1024
#define F_SZ 256
#define D_SZ 64
#define GRID_MAIN 148

// ---------------- device scratch ----------------
__device__ float  g_qkv[3 * F_SZ * D_SZ];    // qkv[t][f][d]
__device__ float  g_trans[2 * F_SZ * D_SZ];  // trans[t][f][d]
__device__ float  g_S1[B_SZ * F_SZ];         // s1[b][j]
__device__ float  g_SA[B_SZ * F_SZ];         // s0*s2 [b][i]
__device__ __half g_Mh[F_SZ * F_SZ];         // gated cross, fp16

// ---------------- smem layout for k_main (bytes) ----------------
#define A_STRH 264                            // halfs per A row (256+8)
#define A_RB   (A_STRH * 2)                   // 528 bytes
#define Z_STRH 72                             // halfs per Z row (64+8)
#define Z_RB   (Z_STRH * 2)                   // 144 bytes
#define SM_A 0                                // 256*528 = 135168
#define SM_Z 135168                           // two buffers of 256*144 = 36864
#define Z_BYTES (F_SZ * Z_RB)
#define SMEM_TOTAL (SM_Z + 2 * Z_BYTES)       // 208896

// ---------------- helpers ----------------
__device__ __forceinline__ uint32_t smem_u32(const void* p) {
    uint32_t a;
    asm("{ .reg .u64 t; cvta.to.shared.u64 t, %1; cvt.u32.u64 %0, t; }"
        : "=r"(a) : "l"(p));
    return a;
}
#define LDSM4(r, a) \
    asm volatile("ldmatrix.sync.aligned.m8n8.x4.shared.b16 {%0,%1,%2,%3}, [%4];" \
                 : "=r"((r)[0]), "=r"((r)[1]), "=r"((r)[2]), "=r"((r)[3]) : "r"(a))
#define LDSM4T(r, a) \
    asm volatile("ldmatrix.sync.aligned.m8n8.x4.trans.shared.b16 {%0,%1,%2,%3}, [%4];" \
                 : "=r"((r)[0]), "=r"((r)[1]), "=r"((r)[2]), "=r"((r)[3]) : "r"(a))
#define HMMA(d, a, b0, b1) \
    asm volatile("mma.sync.aligned.m16n8k16.row.col.f32.f16.f16.f32 " \
                 "{%0,%1,%2,%3}, {%4,%5,%6,%7}, {%8,%9}, {%0,%1,%2,%3};" \
                 : "+f"((d)[0]), "+f"((d)[1]), "+f"((d)[2]), "+f"((d)[3]) \
                 : "r"((a)[0]), "r"((a)[1]), "r"((a)[2]), "r"((a)[3]), \
                   "r"(b0), "r"(b1))

__device__ __forceinline__ uint32_t pack2h(float a, float b) {
    __half2 h = __floats2half2_rn(a, b);
    return *(uint32_t*)&h;
}

// build one Z element (8 halfs = 16 bytes): Z[j][dq*8..dq*8+7]
__device__ __forceinline__ void z_elem(char* zbuf, const float* q2,
                                       const float* s1p, int idx) {
    int j = idx >> 3, dq = idx & 7;
    float s1 = __ldg(s1p + j);
    const float4* qp = (const float4*)(q2 + j * 64) + dq * 2;
    float4 qa = qp[0], qb = qp[1];
    uint4 v;
    v.x = pack2h(qa.x * s1, qa.y * s1);
    v.y = pack2h(qa.z * s1, qa.w * s1);
    v.z = pack2h(qb.x * s1, qb.y * s1);
    v.w = pack2h(qb.z * s1, qb.w * s1);
    *(uint4*)(zbuf + j * Z_RB + dq * 16) = v;
}

// ---------------- K1: qkv / trans = indicator @ W ----------------
__global__ void k_qkv(const float* __restrict__ ind,
                      const float* __restrict__ Wqk,
                      const float* __restrict__ Wqkv) {
    int m = blockIdx.y;
    int fl = threadIdx.x >> 6, e = threadIdx.x & 63;
    int f = blockIdx.x * 4 + fl;
    __shared__ float indS[4 * D_SZ];
    indS[threadIdx.x] = ind[f * D_SZ + e];
    __syncthreads();
    const float* W = (m < 3) ? (Wqkv + m * D_SZ * D_SZ)
                             : (Wqk + (m - 3) * D_SZ * D_SZ);
    float acc = 0.f;
#pragma unroll
    for (int d = 0; d < D_SZ; d++) acc = fmaf(indS[fl * 64 + d], W[d * D_SZ + e], acc);
    if (m < 3) g_qkv[m * F_SZ * D_SZ + f * D_SZ + e] = acc;
    else       g_trans[(m - 3) * F_SZ * D_SZ + f * D_SZ + e] = acc;
}

// ---------------- K2: merged gate + s kernel ----------------
__global__ void __launch_bounds__(256) k_prep(const float* __restrict__ feature) {
    int tid = threadIdx.x, w = tid >> 5, l = tid & 31;
    if (blockIdx.x < 256) {
        int i = blockIdx.x;
        __shared__ float q1i[D_SZ], t0i[D_SZ];
        if (tid < 64) q1i[tid] = g_qkv[F_SZ * D_SZ + i * D_SZ + tid];
        else if (tid < 128) t0i[tid - 64] = g_trans[i * D_SZ + (tid - 64)];
        __syncthreads();
        const float* q0 = g_qkv;
        const float* t1 = g_trans + F_SZ * D_SZ;
        for (int jj = 0; jj < 32; jj++) {
            int j = w * 32 + jj;
            float c  = q1i[l] * q0[j * D_SZ + l] + q1i[l + 32] * q0[j * D_SZ + l + 32];
            float gl = t0i[l] * t1[j * D_SZ + l] + t0i[l + 32] * t1[j * D_SZ + l + 32];
#pragma unroll
            for (int o = 16; o > 0; o >>= 1) {
                c  += __shfl_xor_sync(0xFFFFFFFFu, c, o);
                gl += __shfl_xor_sync(0xFFFFFFFFu, gl, o);
            }
            if (l == 0)
                g_Mh[i * F_SZ + j] = __float2half_rn((gl > 0.f) ? c : 0.f);
        }
    } else {
        int b0 = (blockIdx.x - 256) * 2;
        int hb = l >> 4, ll = l & 15;
        int b = b0 + hb;
        for (int ii = 0; ii < 32; ii++) {
            int i = w * 32 + ii;
            const float4* qp = (const float4*)(g_qkv + i * D_SZ) + ll;
            float4 q0 = qp[0];
            float4 q1 = qp[(F_SZ * D_SZ) / 4];
            float4 q2 = qp[(2 * F_SZ * D_SZ) / 4];
            float4 f = *((const float4*)(feature + (size_t)b * (F_SZ * D_SZ)
                                         + i * D_SZ) + ll);
            float d0 = f.x * q0.x + f.y * q0.y + f.z * q0.z + f.w * q0.w;
            float d1 = f.x * q1.x + f.y * q1.y + f.z * q1.z + f.w * q1.w;
            float d2 = f.x * q2.x + f.y * q2.y + f.z * q2.z + f.w * q2.w;
#pragma unroll
            for (int o = 8; o > 0; o >>= 1) {
                d0 += __shfl_xor_sync(0xFFFFFFFFu, d0, o);
                d1 += __shfl_xor_sync(0xFFFFFFFFu, d1, o);
                d2 += __shfl_xor_sync(0xFFFFFFFFu, d2, o);
            }
            if (ll == 0) {
                g_S1[b * F_SZ + i] = d1;
                g_SA[b * F_SZ + i] = d0 * d2;
            }
        }
    }
}

// ---------------- K3: persistent fp16 HMMA main kernel ----------------
// One unit = one batch; double-buffered Z; Z[b+1] build woven into the
// HMMA mainloop of batch b (1 element/thread at k = 2,6,10,14).
// One __syncthreads per batch.
__global__ void __launch_bounds__(512, 1)
k_main(float* __restrict__ out) {
    extern __shared__ char sm[];
    uint32_t sb = smem_u32(sm);
    int tid = threadIdx.x, w = tid >> 5, lane = tid & 31;
    int c = blockIdx.x;
    int b0 = (c * B_SZ) / GRID_MAIN, b1 = ((c + 1) * B_SZ) / GRID_MAIN;

    // load full M (fp16) into padded smem
    {
        const uint4* msrc = (const uint4*)g_Mh;   // 8 halfs per uint4
        for (int i = tid; i < 8192; i += 512) {
            int r = i >> 5, c8 = i & 31;
            *(uint4*)(sm + SM_A + r * A_RB + c8 * 16) = msrc[i];
        }
    }

    // warp geometry: 16 warps, tile (32 m) x (32 n), full K=256
    int m0 = (w >> 1) * 32, n0 = (w & 1) * 32;
    int g = lane >> 2, t4 = lane & 3;
    uint32_t aBase = sb + SM_A + (uint32_t)(m0 + (lane & 15)) * A_RB
                     + (uint32_t)(lane >> 4) * 16;
    uint32_t bBase0 = sb + SM_Z + (uint32_t)(lane & 15) * Z_RB
                      + (uint32_t)(n0 + 8 * (lane >> 4)) * 2;

    const float* q2 = g_qkv + 2 * F_SZ * D_SZ;

    // initial Z build for batch b0 into buffer 0
    {
        const float* s1p = g_S1 + b0 * F_SZ;
        for (int idx = tid; idx < 2048; idx += 512)
            z_elem(sm + SM_Z, q2, s1p, idx);
    }
    __syncthreads();

    for (int b = b0; b < b1; b++) {
        int cur = (b - b0) & 1, nxt = cur ^ 1;
        uint32_t bBase = bBase0 + (uint32_t)cur * Z_BYTES;
        char* znxt = sm + SM_Z + nxt * Z_BYTES;
        const float* s1n = g_S1 + (b + 1) * F_SZ;
        bool doNext = (b + 1 < b1);

        float acc[8][4];
#pragma unroll
        for (int i = 0; i < 8; i++)
#pragma unroll
            for (int q = 0; q < 4; q++) acc[i][q] = 0.f;

#pragma unroll
        for (int k = 0; k < 16; k++) {
            uint32_t kA = (uint32_t)k * 32;          // 16 halfs along row
            uint32_t kB = (uint32_t)k * 16 * Z_RB;   // 16 Z rows
            uint32_t a0[4], a1[4], bq0[4], bq1[4];
            LDSM4(a0, aBase + kA);
            LDSM4(a1, aBase + 16 * A_RB + kA);
            LDSM4T(bq0, bBase + kB);
            LDSM4T(bq1, bBase + kB + 32);

            HMMA(acc[0], a0, bq0[0], bq0[1]);
            HMMA(acc[1], a0, bq0[2], bq0[3]);
            HMMA(acc[2], a0, bq1[0], bq1[1]);
            HMMA(acc[3], a0, bq1[2], bq1[3]);
            HMMA(acc[4], a1, bq0[0], bq0[1]);
            HMMA(acc[5], a1, bq0[2], bq0[3]);
            HMMA(acc[6], a1, bq1[0], bq1[1]);
            HMMA(acc[7], a1, bq1[2], bq1[3]);

            if ((k & 3) == 2) {                      // k = 2, 6, 10, 14
                if (doNext) z_elem(znxt, q2, s1n, (k >> 2) * 512 + tid);
            }
        }

        // ---- epilogue: scale by SA, direct store ----
        const float* sap = g_SA + b * F_SZ;
        float* ob = out + (size_t)b * (F_SZ * D_SZ);
#pragma unroll
        for (int mt = 0; mt < 2; mt++) {
            int r0 = m0 + mt * 16 + g;
            float f0 = __ldg(sap + r0), f1 = __ldg(sap + r0 + 8);
#pragma unroll
            for (int nt = 0; nt < 4; nt++) {
                float* a = acc[mt * 4 + nt];
                int col = n0 + nt * 8 + 2 * t4;
                *(float2*)(ob + r0 * 64 + col) =
                    make_float2(a[0] * f0, a[1] * f0);
                *(float2*)(ob + (r0 + 8) * 64 + col) =
                    make_float2(a[2] * f1, a[3] * f1);
            }
        }
        __syncthreads();   // Z[b+1] fully written; safe to consume next iter
    }
}

// ---------------- launch ----------------
extern "C" void kernel_launch(void* const* d_in, const int* in_sizes, int n_in,
                              void* d_out, int out_size) {
    const float *feature = nullptr, *indicator = nullptr;
    const float *Wqk = nullptr, *Wqkv = nullptr;
    for (int k = 0; k < n_in; k++) {
        switch (in_sizes[k]) {
            case B_SZ * F_SZ * D_SZ: feature   = (const float*)d_in[k]; break;
            case F_SZ * D_SZ:        indicator = (const float*)d_in[k]; break;
            case 2 * D_SZ * D_SZ:    Wqk       = (const float*)d_in[k]; break;
            case 3 * D_SZ * D_SZ:    Wqkv      = (const float*)d_in[k]; break;
        }
    }
    float* out = (float*)d_out;

    cudaFuncSetAttribute(k_main, cudaFuncAttributeMaxDynamicSharedMemorySize,
                         SMEM_TOTAL);

    k_qkv<<<dim3(64, 5), 256>>>(indicator, Wqk, Wqkv);
    k_prep<<<768, 256>>>(feature);
    k_main<<<GRID_MAIN, 512, SMEM_TOTAL>>>(out);
}